// round 7
// baseline (speedup 1.0000x reference)
#include <cuda_runtime.h>
#include <cstdint>
#include <mma.h>

using namespace nvcuda;

#define NB   4
#define SEQ  1024
#define HID  1024
#define NH   16
#define HDIM 64

// Scratch (device globals; no allocs allowed)
__device__ float g_q[NB * SEQ * HID];
__device__ float g_k[NB * SEQ * HID];
__device__ float g_v[NB * SEQ * HID];
__device__ float g_ctx[NB * SEQ * HID];

// ---------------------------------------------------------------------------
// cp.async helpers
// ---------------------------------------------------------------------------
__device__ __forceinline__ void cp_async16(void* s, const void* g) {
    unsigned sa = (unsigned)__cvta_generic_to_shared(s);
    asm volatile("cp.async.cg.shared.global [%0], [%1], 16;" :: "r"(sa), "l"(g));
}
__device__ __forceinline__ void cp_commit() { asm volatile("cp.async.commit_group;"); }
__device__ __forceinline__ void cp_wait1()  { asm volatile("cp.async.wait_group 1;"); }
__device__ __forceinline__ void cp_wait0()  { asm volatile("cp.async.wait_group 0;"); }

// ---------------------------------------------------------------------------
// Projection GEMM: C = alpha*(A@B + bias). A: MxK row, B: KxN row, C: MxN row.
// 128x128 tile, BK=32, 2-stage cp.async pipeline, 8 warps (2x4). (unchanged)
// ---------------------------------------------------------------------------
#define BM 128
#define BN 128
#define BK 32
#define AST (BK + 4)
#define BST (BN + 4)
#define ASZ (BM * AST)
#define BSZ (BK * BST)
#define GEMM_SMEM ((2 * ASZ + 2 * BSZ) * 4)

__global__ void __launch_bounds__(256, 2)
gemm_proj(const float* __restrict__ A, const float* __restrict__ B,
          float* __restrict__ C, const float* __restrict__ bias,
          float alpha, int M, int N, int K)
{
    extern __shared__ float sm[];
    float* As0 = sm;
    float* As1 = sm + ASZ;
    float* Bs0 = sm + 2 * ASZ;
    float* Bs1 = sm + 2 * ASZ + BSZ;

    const int tid  = threadIdx.x;
    const int warp = tid >> 5;
    const int lane = tid & 31;
    const int wr   = warp >> 2;
    const int wc   = warp & 3;
    const int m0   = blockIdx.y * BM;
    const int n0   = blockIdx.x * BN;

    wmma::fragment<wmma::accumulator, 16, 16, 8, float> acc[4][2];
#pragma unroll
    for (int i = 0; i < 4; i++)
#pragma unroll
        for (int j = 0; j < 2; j++)
            wmma::fill_fragment(acc[i][j], 0.0f);

#define LOAD_STAGE(AP, BP, K0)                                                  \
    {                                                                           \
        _Pragma("unroll")                                                       \
        for (int t = 0; t < 4; t++) {                                           \
            int i = tid + t * 256;                                              \
            int r = i >> 3, kq = i & 7;                                         \
            cp_async16(&(AP)[r * AST + kq * 4],                                 \
                       A + (size_t)(m0 + r) * K + (K0) + kq * 4);               \
        }                                                                       \
        _Pragma("unroll")                                                       \
        for (int t = 0; t < 4; t++) {                                           \
            int i = tid + t * 256;                                              \
            int r = i >> 5, nq = i & 31;                                        \
            cp_async16(&(BP)[r * BST + nq * 4],                                 \
                       B + (size_t)((K0) + r) * N + n0 + nq * 4);               \
        }                                                                       \
    }

    const int nk = K / BK;
    LOAD_STAGE(As0, Bs0, 0);
    cp_commit();

    for (int kt = 0; kt < nk; kt++) {
        float* Acur = (kt & 1) ? As1 : As0;
        float* Bcur = (kt & 1) ? Bs1 : Bs0;
        if (kt + 1 < nk) {
            float* Anx = (kt & 1) ? As0 : As1;
            float* Bnx = (kt & 1) ? Bs0 : Bs1;
            LOAD_STAGE(Anx, Bnx, (kt + 1) * BK);
            cp_commit();
            cp_wait1();
        } else {
            cp_wait0();
        }
        __syncthreads();

#pragma unroll
        for (int kk = 0; kk < BK; kk += 8) {
            wmma::fragment<wmma::matrix_a, 16, 16, 8, wmma::precision::tf32, wmma::row_major> af[4];
            wmma::fragment<wmma::matrix_b, 16, 16, 8, wmma::precision::tf32, wmma::row_major> bf[2];
#pragma unroll
            for (int i = 0; i < 4; i++) {
                wmma::load_matrix_sync(af[i], &Acur[(wr * 64 + i * 16) * AST + kk], AST);
#pragma unroll
                for (int t = 0; t < af[i].num_elements; t++)
                    af[i].x[t] = wmma::__float_to_tf32(af[i].x[t]);
            }
#pragma unroll
            for (int j = 0; j < 2; j++) {
                wmma::load_matrix_sync(bf[j], &Bcur[kk * BST + wc * 32 + j * 16], BST);
#pragma unroll
                for (int t = 0; t < bf[j].num_elements; t++)
                    bf[j].x[t] = wmma::__float_to_tf32(bf[j].x[t]);
            }
#pragma unroll
            for (int i = 0; i < 4; i++)
#pragma unroll
                for (int j = 0; j < 2; j++)
                    wmma::mma_sync(acc[i][j], af[i], bf[j], acc[i][j]);
        }
        __syncthreads();
    }

    float* Cs = sm + warp * 320;
#pragma unroll
    for (int i = 0; i < 4; i++) {
#pragma unroll
        for (int j = 0; j < 2; j++) {
            wmma::store_matrix_sync(Cs, acc[i][j], 20, wmma::mem_row_major);
            __syncwarp();
            int gr0 = m0 + wr * 64 + i * 16;
            int gc0 = n0 + wc * 32 + j * 16;
#pragma unroll
            for (int e = lane; e < 256; e += 32) {
                int r = e >> 4, c = e & 15;
                float v = Cs[r * 20 + c];
                if (bias) v += bias[gc0 + c];
                C[(size_t)(gr0 + r) * N + gc0 + c] = v * alpha;
            }
            __syncwarp();
        }
    }
#undef LOAD_STAGE
}

// ---------------------------------------------------------------------------
// Fused flash attention v2.
//  - warp-private Q stripes: warp w owns S/P/O rows [16w, 16w+16)
//  - exp on accumulator registers (pointwise, layout-agnostic), P RN-rounded
//  - rowsum via ones-column appended to V (col 64 of 80-col V tile)
//  - cp.async double-buffered K/V (+ async Q); tf32 rounding of Q/K/V left to
//    HMMA operand truncation
// ---------------------------------------------------------------------------
#define QST 72
#define KST 72
#define VST 84                              // 80 used cols (64 V + 16 ones-blk), pad 4
#define SST 84                              // P (64 cols) + O spill (80 cols)
#define KSZ (64 * KST)                      // 4608
#define VSZ (64 * VST)                      // 5376
#define QS_OFF 0                            // 128*72 = 9216
#define KS_OFF 9216                         // 2 * 4608 = 9216
#define VS_OFF 18432                        // 2 * 5376 = 10752
#define SS_OFF 29184                        // 128*84  = 10752
#define FLASH_SMEM (39936 * 4)              // 159744 bytes

__global__ void __launch_bounds__(256, 1)
flash_attn(const float* __restrict__ Qg, const float* __restrict__ Kg,
           const float* __restrict__ Vg, float* __restrict__ ctx)
{
    extern __shared__ float sm[];
    const int tid  = threadIdx.x;
    const int warp = tid >> 5;
    const int lane = tid & 31;
    const int qt   = blockIdx.x;          // 0..7
    const int bh   = blockIdx.y;          // 0..63
    const size_t base = (size_t)(bh >> 4) * SEQ * HID + (size_t)(bh & 15) * HDIM;

    // ones-block init for V tiles: cols 64..79, both buffers (col 64 = 1)
#pragma unroll
    for (int t = 0; t < 8; t++) {
        int i = tid + t * 256;            // 0..2047
        int b = i >> 10, r = (i >> 4) & 63, c = i & 15;
        sm[VS_OFF + b * VSZ + r * VST + 64 + c] = (c == 0) ? 1.0f : 0.0f;
    }

    // async Q tile load (128x64) + first K/V stage, one commit group
#pragma unroll
    for (int t = 0; t < 8; t++) {
        int i = tid + t * 256;
        int r = i >> 4, c = i & 15;
        cp_async16(&sm[QS_OFF + r * QST + c * 4],
                   Qg + base + (size_t)(qt * 128 + r) * HID + c * 4);
    }
#define KV_PREFETCH(buf, kvi)                                                   \
    {                                                                           \
        _Pragma("unroll")                                                       \
        for (int t = 0; t < 4; t++) {                                           \
            int i = tid + t * 256;                                              \
            int r = i >> 4, c = i & 15;                                         \
            size_t go = base + (size_t)((kvi) * 64 + r) * HID + c * 4;          \
            cp_async16(&sm[KS_OFF + (buf) * KSZ + r * KST + c * 4], Kg + go);   \
            cp_async16(&sm[VS_OFF + (buf) * VSZ + r * VST + c * 4], Vg + go);   \
        }                                                                       \
    }
    KV_PREFETCH(0, 0);
    cp_commit();

    wmma::fragment<wmma::accumulator, 16, 16, 8, float> oacc[5];
#pragma unroll
    for (int j = 0; j < 5; j++) wmma::fill_fragment(oacc[j], 0.0f);

    float* Pw = &sm[SS_OFF + (warp * 16) * SST];   // this warp's P/O rows

    for (int kv = 0; kv < SEQ / 64; kv++) {
        const int cur = kv & 1;
        if (kv + 1 < SEQ / 64) {
            KV_PREFETCH(cur ^ 1, kv + 1);
            cp_commit();
            cp_wait1();
        } else {
            cp_wait0();
        }
        __syncthreads();   // (a) cur K/V (+Q on iter 0) visible to all

        const float* Ks = &sm[KS_OFF + cur * KSZ];
        const float* Vs = &sm[VS_OFF + cur * VSZ];

        // S = Q @ K^T for this warp's 16 rows, all 64 cols
        wmma::fragment<wmma::accumulator, 16, 16, 8, float> sacc[4];
#pragma unroll
        for (int j = 0; j < 4; j++) wmma::fill_fragment(sacc[j], 0.0f);
#pragma unroll
        for (int kk = 0; kk < 64; kk += 8) {
            wmma::fragment<wmma::matrix_a, 16, 16, 8, wmma::precision::tf32, wmma::row_major> af;
            wmma::load_matrix_sync(af, &sm[QS_OFF + (warp * 16) * QST + kk], QST);
#pragma unroll
            for (int j = 0; j < 4; j++) {
                wmma::fragment<wmma::matrix_b, 16, 16, 8, wmma::precision::tf32, wmma::col_major> bf;
                wmma::load_matrix_sync(bf, &Ks[(j * 16) * KST + kk], KST);
                wmma::mma_sync(sacc[j], af, bf, sacc[j]);
            }
        }
        // P = exp(S) on registers (pointwise), RN-round to tf32, store own rows
#pragma unroll
        for (int j = 0; j < 4; j++) {
#pragma unroll
            for (int t = 0; t < sacc[j].num_elements; t++)
                sacc[j].x[t] = wmma::__float_to_tf32(__expf(sacc[j].x[t]));
            wmma::store_matrix_sync(&Pw[j * 16], sacc[j], SST, wmma::mem_row_major);
        }
        __syncwarp();      // P visible within warp (only this warp reads it)

        // O += P @ [V | ones]
#pragma unroll
        for (int kk = 0; kk < 64; kk += 8) {
            wmma::fragment<wmma::matrix_a, 16, 16, 8, wmma::precision::tf32, wmma::row_major> pa;
            wmma::load_matrix_sync(pa, &Pw[kk], SST);
#pragma unroll
            for (int j = 0; j < 5; j++) {
                wmma::fragment<wmma::matrix_b, 16, 16, 8, wmma::precision::tf32, wmma::row_major> pb;
                wmma::load_matrix_sync(pb, &Vs[kk * VST + j * 16], VST);
                wmma::mma_sync(oacc[j], pa, pb, oacc[j]);
            }
        }
        __syncthreads();   // (c) all reads of cur K/V done before it is re-filled
    }

    // Spill O (incl. rowsum col 64) to own Ss rows, normalize, write out
#pragma unroll
    for (int j = 0; j < 5; j++)
        wmma::store_matrix_sync(&Pw[j * 16], oacc[j], SST, wmma::mem_row_major);
    __syncwarp();
#pragma unroll
    for (int e = 0; e < 8; e++) {
        int i = lane + e * 32;            // 0..255
        int r16 = i >> 4, c4 = i & 15;
        int row = warp * 16 + r16;
        float inv = 1.0f / sm[SS_OFF + row * SST + 64];
        float4 v = *(float4*)&sm[SS_OFF + row * SST + c4 * 4];
        v.x *= inv; v.y *= inv; v.z *= inv; v.w *= inv;
        *(float4*)(ctx + base + (size_t)(qt * 128 + row) * HID + c4 * 4) = v;
    }
#undef KV_PREFETCH
}

// ---------------------------------------------------------------------------
extern "C" void kernel_launch(void* const* d_in, const int* in_sizes, int n_in,
                              void* d_out, int out_size)
{
    const float* v_hid = (const float*)d_in[0];
    const float* l_hid = (const float*)d_in[1];
    const float* q_w   = (const float*)d_in[2];
    const float* q_b   = (const float*)d_in[3];
    const float* k_w   = (const float*)d_in[4];
    const float* k_b   = (const float*)d_in[5];
    const float* v_w   = (const float*)d_in[6];
    const float* v_b   = (const float*)d_in[7];
    const float* o_w   = (const float*)d_in[8];
    const float* o_b   = (const float*)d_in[9];
    float* out = (float*)d_out;

    void *pq, *pk, *pv, *pctx;
    cudaGetSymbolAddress(&pq, g_q);
    cudaGetSymbolAddress(&pk, g_k);
    cudaGetSymbolAddress(&pv, g_v);
    cudaGetSymbolAddress(&pctx, g_ctx);
    float* q   = (float*)pq;
    float* k   = (float*)pk;
    float* v   = (float*)pv;
    float* ctx = (float*)pctx;

    cudaFuncSetAttribute(gemm_proj, cudaFuncAttributeMaxDynamicSharedMemorySize, GEMM_SMEM);
    cudaFuncSetAttribute(flash_attn, cudaFuncAttributeMaxDynamicSharedMemorySize, FLASH_SMEM);

    const int M = NB * SEQ;
    dim3 pg(HID / BN, M / BM);

    // Q/K/V projections (1/32 score scale folded into Q)
    gemm_proj<<<pg, 256, GEMM_SMEM>>>(l_hid, q_w, q, q_b, 1.0f / 32.0f, M, HID, HID);
    gemm_proj<<<pg, 256, GEMM_SMEM>>>(v_hid, k_w, k, k_b, 1.0f,         M, HID, HID);
    gemm_proj<<<pg, 256, GEMM_SMEM>>>(v_hid, v_w, v, v_b, 1.0f,         M, HID, HID);

    // Fused attention
    flash_attn<<<dim3(SEQ / 128, NB * NH), 256, FLASH_SMEM>>>(q, k, v, ctx);

    // Output projection
    gemm_proj<<<pg, 256, GEMM_SMEM>>>(ctx, o_w, out, o_b, 1.0f, M, HID, HID);
}